// round 11
// baseline (speedup 1.0000x reference)
#include <cuda_runtime.h>
#include <cuda_bf16.h>
#include <math.h>
#include <stdint.h>

#define NB   8
#define L    5000
#define DIN  12
#define H    256
#define N2   32
#define NL   6
#define NC   64
#define CT   79
#define BL   (NB*L)
#define BLP  40064
#define NP   16

typedef unsigned long long ull;

__device__ __forceinline__ ull fma2(ull a, ull b, ull c){ ull d; asm("fma.rn.f32x2 %0,%1,%2,%3;":"=l"(d):"l"(a),"l"(b),"l"(c)); return d; }
__device__ __forceinline__ ull mul2(ull a, ull b){ ull d; asm("mul.rn.f32x2 %0,%1,%2;":"=l"(d):"l"(a),"l"(b)); return d; }
__device__ __forceinline__ ull pk2(float lo, float hi){ ull r; asm("mov.b64 %0,{%1,%2};":"=l"(r):"f"(lo),"f"(hi)); return r; }
__device__ __forceinline__ void upk2(ull v, float& lo, float& hi){ asm("mov.b64 {%0,%1},%2;":"=f"(lo),"=f"(hi):"l"(v)); }
__device__ __forceinline__ void cpa16(uint32_t dst, const void* src){
    asm volatile("cp.async.cg.shared.global [%0], [%1], 16;"::"r"(dst),"l"(src));
}
__device__ __forceinline__ void cpa_commit(){ asm volatile("cp.async.commit_group;"); }
__device__ __forceinline__ void cpa_wait0(){ asm volatile("cp.async.wait_group 0;"); }
__device__ __forceinline__ float gelu1(float y){ return 0.5f*y*(1.0f + erff(y*0.70710678118654752f)); }
__device__ __forceinline__ uint32_t smem_u32(const void* p){
    uint32_t a; asm("{ .reg .u64 t; cvta.to.shared.u64 t, %1; cvt.u32.u64 %0, t; }":"=r"(a):"l"(p)); return a;
}
__device__ __forceinline__ void mma16816(float* d, const uint32_t* a, const uint32_t* b){
    asm volatile("mma.sync.aligned.m16n8k16.row.col.f32.bf16.bf16.f32 "
        "{%0,%1,%2,%3}, {%4,%5,%6,%7}, {%8,%9}, {%0,%1,%2,%3};"
        : "+f"(d[0]),"+f"(d[1]),"+f"(d[2]),"+f"(d[3])
        : "r"(a[0]),"r"(a[1]),"r"(a[2]),"r"(a[3]), "r"(b[0]),"r"(b[1]));
}
__device__ __forceinline__ void ldsm_x4(uint32_t* r, uint32_t addr){
    asm volatile("ldmatrix.sync.aligned.m8n8.x4.shared.b16 {%0,%1,%2,%3}, [%4];"
        : "=r"(r[0]),"=r"(r[1]),"=r"(r[2]),"=r"(r[3]) : "r"(addr));
}
__device__ __forceinline__ void ldsm_x2(uint32_t* r, uint32_t addr){
    asm volatile("ldmatrix.sync.aligned.m8n8.x2.shared.b16 {%0,%1}, [%2];"
        : "=r"(r[0]),"=r"(r[1]) : "r"(addr));
}

// ---- scratch ----
__device__ float  g_h[NB*H*L];
__device__ float  g_yg[H*BL + 128];
__device__ __nv_bfloat16 g_ybT_hi[BLP*H];
__device__ __nv_bfloat16 g_ybT_lo[BLP*H];
__device__ __nv_bfloat16 g_wh[NL*2*H*H];
__device__ __nv_bfloat16 g_wl[NL*2*H*H];
__device__ float4 g_pk1[NL*H*NP];
__device__ float4 g_pk2[NL*H*NP];
__device__ float2 g_pk3[NL*H*NP];
__device__ float2 g_r  [NL*H*N2];
__device__ float  g_bnscale[H];
__device__ float  g_bnshift[H];
__device__ double g_bnsum[H];
__device__ double g_bnsq[H];

__global__ void params_kernel(const float* __restrict__ log_dt, const float* __restrict__ C_re,
                              const float* __restrict__ C_im, const float* __restrict__ logA,
                              const float* __restrict__ Aim){
    int idx = blockIdx.x*blockDim.x + threadIdx.x;
    if (idx >= NL*H*NP) return;
    int np = idx & (NP-1);
    int lh = idx >> 4;
    float dt = expf(log_dt[lh]);
    float rr[2], ri[2], cr[2], ci[2];
#pragma unroll
    for (int k = 0; k < 2; k++){
        int pi = lh*N2 + np + k*16;
        float Ar = -expf(logA[pi]);
        float Ai = Aim[pi];
        float er = expf(dt*Ar);
        float rre = er*cosf(dt*Ai), rim = er*sinf(dt*Ai);
        float e1r = rre - 1.0f, e1i = rim;
        float cre = C_re[pi], cim = C_im[pi];
        float tr = cre*e1r - cim*e1i;
        float ti = cre*e1i + cim*e1r;
        float inv = 1.0f/(Ar*Ar + Ai*Ai);
        float Cdr = (tr*Ar + ti*Ai)*inv;
        float Cdi = (ti*Ar - tr*Ai)*inv;
        rr[k]=rre; ri[k]=rim; cr[k]=2.0f*Cdr; ci[k]=2.0f*Cdi;
        g_r[pi] = make_float2(rre, rim);
    }
    g_pk1[idx] = make_float4(rr[0], rr[1], ri[0], ri[1]);
    g_pk2[idx] = make_float4(-ri[0], -ri[1], cr[0], cr[1]);
    g_pk3[idx] = make_float2(ci[0], ci[1]);
}

__global__ void wconv_kernel(const float* __restrict__ Wg){
    int idx = blockIdx.x*blockDim.x + threadIdx.x;
    if (idx >= NL*2*H*H) return;
    float w = Wg[idx];
    __nv_bfloat16 hi = __float2bfloat16_rn(w);
    g_wh[idx] = hi;
    g_wl[idx] = __float2bfloat16_rn(w - __bfloat162float(hi));
}

__global__ void preproj_kernel(const float* __restrict__ x, const float* __restrict__ w,
                               const float* __restrict__ bias){
    __shared__ float xs[128*13];
    __shared__ float ws[H*12];
    __shared__ float bs[H];
    int b = blockIdx.y;
    int l0 = blockIdx.x*128;
    int tid = threadIdx.x;
    for (int i = tid; i < H*12; i += 128) ws[i] = w[i];
    for (int i = tid; i < H;    i += 128) bs[i] = bias[i];
    for (int i = tid; i < 128*12; i += 128){
        int ll = i/12, d = i - ll*12;
        int l = l0 + ll;
        xs[ll*13+d] = (l < L) ? x[(b*L + l)*12 + d] : 0.0f;
    }
    __syncthreads();
    int l = l0 + tid;
    if (l >= L) return;
    float xv[12];
#pragma unroll
    for (int d = 0; d < 12; d++) xv[d] = xs[tid*13+d];
    for (int h = 0; h < H; h++){
        float acc = bs[h];
#pragma unroll
        for (int d = 0; d < 12; d++) acc = fmaf(xv[d], ws[h*12+d], acc);
        g_h[(b*H + h)*L + l] = acc;
    }
}

__device__ __forceinline__ void cpow79(float br, float bi, float& pr, float& pi){
    float ar = br, ai = bi;
    float xr = br, xi = bi;
#pragma unroll
    for (int s = 1; s <= 6; s++){
        float nr = xr*xr - xi*xi;
        float ni = 2.0f*xr*xi;
        xr = nr; xi = ni;
        if (s==1 || s==2 || s==3 || s==6){
            float tr = ar*xr - ai*xi;
            float ti = ar*xi + ai*xr;
            ar = tr; ai = ti;
        }
    }
    pr = ar; pi = ai;
}

// fused 3-phase chunked scan + D-skip + GELU; phase-C shuffles batched x4
__global__ __launch_bounds__(256) void scan_fused_kernel(int layer, const float* __restrict__ Dp,
                                                         int do_bn){
    __shared__ float  su[L];
    __shared__ float4 sf[NC][NP+1];
    int bh  = blockIdx.x;
    int h   = bh & (H-1);
    int tid = threadIdx.x;
    int lh  = layer*H + h;
    int c = tid >> 2, q = tid & 3;

    ull rrv[4], riv[4], nriv[4], crv[4], civ[4];
#pragma unroll
    for (int k = 0; k < 4; k++){
        int np = q*4 + k;
        float4 p1 = g_pk1[lh*NP + np];
        float4 p2 = g_pk2[lh*NP + np];
        float2 p3 = g_pk3[lh*NP + np];
        rrv[k]  = pk2(p1.x, p1.y);
        riv[k]  = pk2(p1.z, p1.w);
        nriv[k] = pk2(p2.x, p2.y);
        crv[k]  = pk2(p2.z, p2.w);
        civ[k]  = pk2(p3.x, p3.y);
    }
    float Dh  = Dp[lh];
    float bsc = do_bn ? g_bnscale[h] : 1.0f;
    float bsh = do_bn ? g_bnshift[h] : 0.0f;
    const float4* urow = (const float4*)(g_h + bh*L);
    for (int i = tid; i < L/4; i += 256){
        float4 v = urow[i];
        v.x = fmaf(v.x, bsc, bsh); v.y = fmaf(v.y, bsc, bsh);
        v.z = fmaf(v.z, bsc, bsh); v.w = fmaf(v.w, bsc, bsh);
        *(float4*)&su[i*4] = v;
    }
    __syncthreads();

    int off = c*CT;
    int Tc  = min(CT, L - off);

    ull sr[4], sti[4];
#pragma unroll
    for (int k = 0; k < 4; k++){ sr[k]=0ull; sti[k]=0ull; }

    for (int t = 0; t < Tc; t++){
        float uv = su[off + t];
        ull uu = pk2(uv, uv);
#pragma unroll
        for (int k = 0; k < 4; k++){
            ull tmp = fma2(riv[k], sti[k], uu);
            ull m   = mul2(nriv[k], sr[k]);
            sti[k]  = fma2(rrv[k], sti[k], m);
            sr[k]   = fma2(rrv[k], sr[k], tmp);
        }
    }
#pragma unroll
    for (int k = 0; k < 4; k++){
        float s0,s1,ta,tb; upk2(sr[k],s0,s1); upk2(sti[k],ta,tb);
        sf[c][q*4+k] = make_float4(s0, s1, ta, tb);
    }
    __syncthreads();

    if (tid < NP){
        int np = tid;
        float2 r0 = g_r[lh*N2 + np];
        float2 r1 = g_r[lh*N2 + np + 16];
        float a0r, a0i, a1r, a1i;
        cpow79(r0.x, r0.y, a0r, a0i);
        cpow79(r1.x, r1.y, a1r, a1i);
        float s0r=0.f, s0t=0.f, s1r=0.f, s1t=0.f;
        for (int c2 = 0; c2 < NC; c2++){
            float4 f = sf[c2][np];
            sf[c2][np] = make_float4(s0r, s1r, s0t, s1t);
            float n0r = a0r*s0r + a0i*s0t + f.x;
            float n0t = a0r*s0t - a0i*s0r + f.z;
            float n1r = a1r*s1r + a1i*s1t + f.y;
            float n1t = a1r*s1t - a1i*s1r + f.w;
            s0r=n0r; s0t=n0t; s1r=n1r; s1t=n1t;
        }
    }
    __syncthreads();

#pragma unroll
    for (int k = 0; k < 4; k++){
        float4 v = sf[c][q*4+k];
        sr[k]  = pk2(v.x, v.y);
        sti[k] = pk2(v.z, v.w);
    }
    int t = 0;
    for (int g = 0; g < 19; g++){
        float yp[4], us[4];
#pragma unroll
        for (int i = 0; i < 4; i++){
            int idx = off + t + i;
            float uv = su[idx < L ? idx : (L-1)];
            us[i] = uv;
            ull uu = pk2(uv, uv);
            ull y2 = 0ull;
#pragma unroll
            for (int k = 0; k < 4; k++){
                ull tmp = fma2(riv[k], sti[k], uu);
                ull m   = mul2(nriv[k], sr[k]);
                sti[k]  = fma2(rrv[k], sti[k], m);
                sr[k]   = fma2(rrv[k], sr[k], tmp);
                y2 = fma2(crv[k], sr[k], y2);
                y2 = fma2(civ[k], sti[k], y2);
            }
            float ylo, yhi; upk2(y2, ylo, yhi);
            yp[i] = ylo + yhi;
        }
#pragma unroll
        for (int i = 0; i < 4; i++) yp[i] += __shfl_xor_sync(0xffffffffu, yp[i], 1);
#pragma unroll
        for (int i = 0; i < 4; i++) yp[i] += __shfl_xor_sync(0xffffffffu, yp[i], 2);
#pragma unroll
        for (int i = 0; i < 4; i++){
            int idx = off + t + i;
            if (idx < L) su[idx] = fmaf(us[i], Dh, yp[i]);
        }
        t += 4;
    }
#pragma unroll
    for (int i = 0; i < 3; i++){
        int idx = off + 76 + i;
        float uv = su[idx < L ? idx : (L-1)];
        ull uu = pk2(uv, uv);
        ull y2 = 0ull;
#pragma unroll
        for (int k = 0; k < 4; k++){
            ull tmp = fma2(riv[k], sti[k], uu);
            ull m   = mul2(nriv[k], sr[k]);
            sti[k]  = fma2(rrv[k], sti[k], m);
            sr[k]   = fma2(rrv[k], sr[k], tmp);
            y2 = fma2(crv[k], sr[k], y2);
            y2 = fma2(civ[k], sti[k], y2);
        }
        float ylo, yhi; upk2(y2, ylo, yhi);
        float y = ylo + yhi;
        y += __shfl_xor_sync(0xffffffffu, y, 1);
        y += __shfl_xor_sync(0xffffffffu, y, 2);
        if (idx < L) su[idx] = fmaf(uv, Dh, y);
    }
    __syncthreads();

    float4* orow = (float4*)(g_yg + h*BL + (bh >> 8)*L);
    for (int i = tid; i < L/4; i += 256){
        float4 v = *(const float4*)&su[i*4];
        v.x = gelu1(v.x); v.y = gelu1(v.y); v.z = gelu1(v.z); v.w = gelu1(v.w);
        orow[i] = v;
    }
}

// transpose + bf16-split: g_yg fp32 [k=256][BL] -> g_ybT_{hi,lo} bf16 [BLP][256]
__global__ __launch_bounds__(256) void ytr_kernel(){
    __shared__ float ts[64][65];
    int jt = blockIdx.x;
    int kt = blockIdx.y;
    int tid = threadIdx.x;
    int kr = tid >> 4, jc = tid & 15;
#pragma unroll
    for (int it = 0; it < 4; it++){
        int kk = kr + it*16;
        int k = kt*64 + kk;
        int j = jt*64 + jc*4;
        float4 v = make_float4(0.f,0.f,0.f,0.f);
        if (j < BL) v = *(const float4*)&g_yg[k*BL + j];
        ts[kk][jc*4+0]=v.x; ts[kk][jc*4+1]=v.y; ts[kk][jc*4+2]=v.z; ts[kk][jc*4+3]=v.w;
    }
    __syncthreads();
    int jr = tid >> 2, ks = (tid & 3)*16;
    int j = jt*64 + jr;
    uint32_t ph[8], pl[8];
#pragma unroll
    for (int i = 0; i < 8; i++){
        float v0 = ts[ks + i*2    ][jr];
        float v1 = ts[ks + i*2 + 1][jr];
        __nv_bfloat16 h0 = __float2bfloat16_rn(v0);
        __nv_bfloat16 h1 = __float2bfloat16_rn(v1);
        __nv_bfloat16 l0 = __float2bfloat16_rn(v0 - __bfloat162float(h0));
        __nv_bfloat16 l1 = __float2bfloat16_rn(v1 - __bfloat162float(h1));
        ph[i] = ((uint32_t)__bfloat16_as_ushort(h1) << 16) | __bfloat16_as_ushort(h0);
        pl[i] = ((uint32_t)__bfloat16_as_ushort(l1) << 16) | __bfloat16_as_ushort(l0);
    }
    uint4* dh = (uint4*)(g_ybT_hi + j*H + kt*64 + ks);
    uint4* dl = (uint4*)(g_ybT_lo + j*H + kt*64 + ks);
    dh[0] = make_uint4(ph[0],ph[1],ph[2],ph[3]);
    dh[1] = make_uint4(ph[4],ph[5],ph[6],ph[7]);
    dl[0] = make_uint4(pl[0],pl[1],pl[2],pl[3]);
    dl[1] = make_uint4(pl[4],pl[5],pl[6],pl[7]);
}

// bf16-split mma.sync GEMM + GLU + BN-residual epilogue
#define SM_AHI 0
#define SM_ALO 16384
#define SM_BHI 32768
#define SM_BLO 49152
#define SM_TOT 65536

__global__ __launch_bounds__(256) void mma_gemm_kernel(const float* __restrict__ bias,
                                                       int layer, int do_bn){
    extern __shared__ char smem[];
    uint32_t sb = smem_u32(smem);
    float* ex = (float*)smem;           // reused post-mainloop (64x132 f32)
    int tid = threadIdx.x;
    int wid = tid >> 5, lane = tid & 31;
    int warp_m = wid >> 2, warp_n = wid & 3;
    int j0 = blockIdx.x * 128;
    int g0 = blockIdx.y;
    const float* bl = bias + layer*2*H;
    const __nv_bfloat16* whL = g_wh + layer*2*H*H;
    const __nv_bfloat16* wlL = g_wl + layer*2*H*H;

    float acc[4][4][4];
#pragma unroll
    for (int mf = 0; mf < 4; mf++)
#pragma unroll
        for (int nf = 0; nf < 4; nf++)
#pragma unroll
            for (int c2 = 0; c2 < 4; c2++) acc[mf][nf][c2] = 0.0f;

    // ldmatrix lane geometry
    int a_r    = ((lane>>3)&1)*8 + (lane&7);
    int a_kadd = lane>>4;
    int a_sw   = a_r & 7;
    int b_r    = lane & 7;
    int b_kadd = (lane>>3)&1;
    int b_sw   = b_r & 7;

    for (int kc = 0; kc < 4; kc++){
#pragma unroll
        for (int t = 0; t < 4; t++){
            int u = tid + t*256;
            int r = u >> 3, uu = u & 7;
            uint32_t off = (uint32_t)(r*128 + ((uu ^ (r&7))*16));
            int wr = (r < 64) ? (g0*64 + r) : (192 + g0*64 + r);
            cpa16(sb + SM_AHI + off, whL + (wr*H + kc*64 + uu*8));
            cpa16(sb + SM_ALO + off, wlL + (wr*H + kc*64 + uu*8));
            cpa16(sb + SM_BHI + off, g_ybT_hi + ((size_t)(j0 + r)*H + kc*64 + uu*8));
            cpa16(sb + SM_BLO + off, g_ybT_lo + ((size_t)(j0 + r)*H + kc*64 + uu*8));
        }
        cpa_commit(); cpa_wait0();
        __syncthreads();
#pragma unroll
        for (int k16 = 0; k16 < 4; k16++){
            uint32_t bh[4][2], blo[4][2];
#pragma unroll
            for (int nf = 0; nf < 4; nf++){
                int jl = warp_n*32 + nf*8 + b_r;
                uint32_t boff = (uint32_t)(jl*128 + (((k16*2 + b_kadd) ^ b_sw)*16));
                ldsm_x2(bh[nf],  sb + SM_BHI + boff);
                ldsm_x2(blo[nf], sb + SM_BLO + boff);
            }
#pragma unroll
            for (int mf = 0; mf < 4; mf++){
                int row = warp_m*64 + mf*16 + a_r;
                uint32_t aoff = (uint32_t)(row*128 + (((k16*2 + a_kadd) ^ a_sw)*16));
                uint32_t ah[4], al[4];
                ldsm_x4(ah, sb + SM_AHI + aoff);
                ldsm_x4(al, sb + SM_ALO + aoff);
#pragma unroll
                for (int nf = 0; nf < 4; nf++){
                    mma16816(acc[mf][nf], ah, bh[nf]);
                    mma16816(acc[mf][nf], ah, blo[nf]);
                    mma16816(acc[mf][nf], al, bh[nf]);
                }
            }
        }
        __syncthreads();
    }

    int gr = lane >> 2, gc2 = (lane & 3)*2;
    if (warp_m == 1){
#pragma unroll
        for (int mf = 0; mf < 4; mf++)
#pragma unroll
        for (int nf = 0; nf < 4; nf++)
#pragma unroll
        for (int c2 = 0; c2 < 4; c2++){
            int rl = mf*16 + gr + (c2>>1)*8;
            int col = warp_n*32 + nf*8 + gc2 + (c2&1);
            ex[rl*132 + col] = acc[mf][nf][c2];
        }
    }
    __syncthreads();
    if (warp_m == 0){
#pragma unroll
        for (int mf = 0; mf < 4; mf++)
#pragma unroll
        for (int nf = 0; nf < 4; nf++)
#pragma unroll
        for (int c2 = 0; c2 < 4; c2++){
            int rl = mf*16 + gr + (c2>>1)*8;
            int col = warp_n*32 + nf*8 + gc2 + (c2&1);
            int ga = g0*64 + rl;
            float a = acc[mf][nf][c2] + bl[ga];
            float b = ex[rl*132 + col] + bl[256 + ga];
            float glu = a * (1.0f/(1.0f + expf(-b)));
            int j = j0 + col;
            if (j < BL){
                int bb = j / L, l = j - bb*L;
                int idx = (bb*H + ga)*L + l;
                float sc = do_bn ? g_bnscale[ga] : 1.0f;
                float sh = do_bn ? g_bnshift[ga] : 0.0f;
                g_h[idx] = fmaf(g_h[idx], sc, sh) + glu;
            }
        }
    }
}

__global__ void bn_stats_kernel(){
    __shared__ double ssum[256], ssq[256];
    int h = blockIdx.x;
    int half = blockIdx.y;
    int tid = threadIdx.x;
    double s = 0.0, q = 0.0;
    for (int i = tid; i < 4*L; i += 256){
        int b = half*4 + i / L, l = i % L;
        float v = g_h[(b*H + h)*L + l];
        s += v; q += (double)v*(double)v;
    }
    ssum[tid] = s; ssq[tid] = q;
    __syncthreads();
    for (int st = 128; st > 0; st >>= 1){
        if (tid < st){ ssum[tid] += ssum[tid+st]; ssq[tid] += ssq[tid+st]; }
        __syncthreads();
    }
    if (tid == 0){
        atomicAdd(&g_bnsum[h], ssum[0]);
        atomicAdd(&g_bnsq[h],  ssq[0]);
    }
}

__global__ void bn_finalize_kernel(const float* __restrict__ gamma, const float* __restrict__ beta,
                                   int bnidx){
    int h = threadIdx.x;
    double mean = g_bnsum[h] / (double)(NB*L);
    double var  = g_bnsq[h] / (double)(NB*L) - mean*mean;
    float scale = gamma[bnidx*H + h] * (float)(1.0 / sqrt(var + 1e-5));
    g_bnscale[h] = scale;
    g_bnshift[h] = beta[bnidx*H + h] - (float)mean * scale;
    g_bnsum[h] = 0.0;
    g_bnsq[h]  = 0.0;
}

__global__ void transpose_kernel(float* __restrict__ out){
    __shared__ float tile[32][33];
    int b = blockIdx.z;
    int l0 = blockIdx.x*32, h0 = blockIdx.y*32;
    int tx = threadIdx.x, ty = threadIdx.y;
    for (int i = ty; i < 32; i += 8){
        int l = l0 + tx;
        tile[i][tx] = (l < L) ? g_h[(b*H + h0 + i)*L + l] : 0.0f;
    }
    __syncthreads();
    for (int i = ty; i < 32; i += 8){
        int l = l0 + i;
        if (l < L) out[(b*L + l)*H + h0 + tx] = tile[tx][i];
    }
}

extern "C" void kernel_launch(void* const* d_in, const int* in_sizes, int n_in,
                              void* d_out, int out_size){
    const float* x      = (const float*)d_in[0];
    const float* pre_w  = (const float*)d_in[1];
    const float* pre_b  = (const float*)d_in[2];
    const float* log_dt = (const float*)d_in[3];
    const float* C_re   = (const float*)d_in[4];
    const float* C_im   = (const float*)d_in[5];
    const float* logA   = (const float*)d_in[6];
    const float* Aim    = (const float*)d_in[7];
    const float* Dp     = (const float*)d_in[8];
    const float* out_w  = (const float*)d_in[9];
    const float* out_b  = (const float*)d_in[10];
    const float* bn_g   = (const float*)d_in[11];
    const float* bn_b   = (const float*)d_in[12];
    float* out = (float*)d_out;

    cudaFuncSetAttribute(mma_gemm_kernel, cudaFuncAttributeMaxDynamicSharedMemorySize, SM_TOT);

    params_kernel<<<96, 256>>>(log_dt, C_re, C_im, logA, Aim);
    wconv_kernel<<<(NL*2*H*H + 255)/256, 256>>>(out_w);
    preproj_kernel<<<dim3(40, 8), 128>>>(x, pre_w, pre_b);
    for (int layer = 0; layer < NL; layer++){
        int do_bn = (layer > 0) && (((layer - 1) & 1) == 0);
        scan_fused_kernel<<<NB*H, 256>>>(layer, Dp, do_bn);
        ytr_kernel<<<dim3(BLP/64, 4), 256>>>();
        mma_gemm_kernel<<<dim3(BLP/128, 4), 256, SM_TOT>>>(out_b, layer, do_bn);
        if ((layer & 1) == 0){
            bn_stats_kernel<<<dim3(H, 2), 256>>>();
            bn_finalize_kernel<<<1, H>>>(bn_g, bn_b, layer/2);
        }
    }
    transpose_kernel<<<dim3((L + 31)/32, H/32, NB), dim3(32, 8)>>>(out);
}

// round 12
// speedup vs baseline: 1.0044x; 1.0044x over previous
#include <cuda_runtime.h>
#include <cuda_bf16.h>
#include <math.h>
#include <stdint.h>

#define NB   8
#define L    5000
#define DIN  12
#define H    256
#define N2   32
#define NL   6
#define NC   64
#define CT   79
#define BL   (NB*L)
#define BLP  40064
#define NP   16

typedef unsigned long long ull;

__device__ __forceinline__ ull fma2(ull a, ull b, ull c){ ull d; asm("fma.rn.f32x2 %0,%1,%2,%3;":"=l"(d):"l"(a),"l"(b),"l"(c)); return d; }
__device__ __forceinline__ ull mul2(ull a, ull b){ ull d; asm("mul.rn.f32x2 %0,%1,%2;":"=l"(d):"l"(a),"l"(b)); return d; }
__device__ __forceinline__ ull pk2(float lo, float hi){ ull r; asm("mov.b64 %0,{%1,%2};":"=l"(r):"f"(lo),"f"(hi)); return r; }
__device__ __forceinline__ void upk2(ull v, float& lo, float& hi){ asm("mov.b64 {%0,%1},%2;":"=f"(lo),"=f"(hi):"l"(v)); }
__device__ __forceinline__ void cpa16(uint32_t dst, const void* src){
    asm volatile("cp.async.cg.shared.global [%0], [%1], 16;"::"r"(dst),"l"(src));
}
__device__ __forceinline__ void cpa_commit(){ asm volatile("cp.async.commit_group;"); }
__device__ __forceinline__ void cpa_wait0(){ asm volatile("cp.async.wait_group 0;"); }
__device__ __forceinline__ float gelu1(float y){ return 0.5f*y*(1.0f + erff(y*0.70710678118654752f)); }
__device__ __forceinline__ uint32_t smem_u32(const void* p){
    uint32_t a; asm("{ .reg .u64 t; cvta.to.shared.u64 t, %1; cvt.u32.u64 %0, t; }":"=r"(a):"l"(p)); return a;
}
__device__ __forceinline__ void mma16816(float* d, const uint32_t* a, const uint32_t* b){
    asm volatile("mma.sync.aligned.m16n8k16.row.col.f32.bf16.bf16.f32 "
        "{%0,%1,%2,%3}, {%4,%5,%6,%7}, {%8,%9}, {%0,%1,%2,%3};"
        : "+f"(d[0]),"+f"(d[1]),"+f"(d[2]),"+f"(d[3])
        : "r"(a[0]),"r"(a[1]),"r"(a[2]),"r"(a[3]), "r"(b[0]),"r"(b[1]));
}
__device__ __forceinline__ void ldsm_x4(uint32_t* r, uint32_t addr){
    asm volatile("ldmatrix.sync.aligned.m8n8.x4.shared.b16 {%0,%1,%2,%3}, [%4];"
        : "=r"(r[0]),"=r"(r[1]),"=r"(r[2]),"=r"(r[3]) : "r"(addr));
}
__device__ __forceinline__ void ldsm_x2(uint32_t* r, uint32_t addr){
    asm volatile("ldmatrix.sync.aligned.m8n8.x2.shared.b16 {%0,%1}, [%2];"
        : "=r"(r[0]),"=r"(r[1]) : "r"(addr));
}

// ---- scratch ----
__device__ float  g_h[NB*H*L];
__device__ float  g_yg[H*BL + 128];
__device__ __nv_bfloat16 g_ybT_hi[BLP*H];
__device__ __nv_bfloat16 g_ybT_lo[BLP*H];
__device__ __nv_bfloat16 g_wh[NL*2*H*H];
__device__ __nv_bfloat16 g_wl[NL*2*H*H];
__device__ float4 g_pk1[NL*H*NP];
__device__ float4 g_pk2[NL*H*NP];
__device__ float2 g_pk3[NL*H*NP];
__device__ float2 g_r  [NL*H*N2];
__device__ float  g_bnscale[H];
__device__ float  g_bnshift[H];
__device__ double g_bnsum[H];
__device__ double g_bnsq[H];

__global__ void params_kernel(const float* __restrict__ log_dt, const float* __restrict__ C_re,
                              const float* __restrict__ C_im, const float* __restrict__ logA,
                              const float* __restrict__ Aim){
    int idx = blockIdx.x*blockDim.x + threadIdx.x;
    if (idx >= NL*H*NP) return;
    int np = idx & (NP-1);
    int lh = idx >> 4;
    float dt = expf(log_dt[lh]);
    float rr[2], ri[2], cr[2], ci[2];
#pragma unroll
    for (int k = 0; k < 2; k++){
        int pi = lh*N2 + np + k*16;
        float Ar = -expf(logA[pi]);
        float Ai = Aim[pi];
        float er = expf(dt*Ar);
        float rre = er*cosf(dt*Ai), rim = er*sinf(dt*Ai);
        float e1r = rre - 1.0f, e1i = rim;
        float cre = C_re[pi], cim = C_im[pi];
        float tr = cre*e1r - cim*e1i;
        float ti = cre*e1i + cim*e1r;
        float inv = 1.0f/(Ar*Ar + Ai*Ai);
        float Cdr = (tr*Ar + ti*Ai)*inv;
        float Cdi = (ti*Ar - tr*Ai)*inv;
        rr[k]=rre; ri[k]=rim; cr[k]=2.0f*Cdr; ci[k]=2.0f*Cdi;
        g_r[pi] = make_float2(rre, rim);
    }
    g_pk1[idx] = make_float4(rr[0], rr[1], ri[0], ri[1]);
    g_pk2[idx] = make_float4(-ri[0], -ri[1], cr[0], cr[1]);
    g_pk3[idx] = make_float2(ci[0], ci[1]);
}

__global__ void wconv_kernel(const float* __restrict__ Wg){
    int idx = blockIdx.x*blockDim.x + threadIdx.x;
    if (idx >= NL*2*H*H) return;
    float w = Wg[idx];
    __nv_bfloat16 hi = __float2bfloat16_rn(w);
    g_wh[idx] = hi;
    g_wl[idx] = __float2bfloat16_rn(w - __bfloat162float(hi));
}

__global__ void preproj_kernel(const float* __restrict__ x, const float* __restrict__ w,
                               const float* __restrict__ bias){
    __shared__ float xs[128*13];
    __shared__ float ws[H*12];
    __shared__ float bs[H];
    int b = blockIdx.y;
    int l0 = blockIdx.x*128;
    int tid = threadIdx.x;
    for (int i = tid; i < H*12; i += 128) ws[i] = w[i];
    for (int i = tid; i < H;    i += 128) bs[i] = bias[i];
    for (int i = tid; i < 128*12; i += 128){
        int ll = i/12, d = i - ll*12;
        int l = l0 + ll;
        xs[ll*13+d] = (l < L) ? x[(b*L + l)*12 + d] : 0.0f;
    }
    __syncthreads();
    int l = l0 + tid;
    if (l >= L) return;
    float xv[12];
#pragma unroll
    for (int d = 0; d < 12; d++) xv[d] = xs[tid*13+d];
    for (int h = 0; h < H; h++){
        float acc = bs[h];
#pragma unroll
        for (int d = 0; d < 12; d++) acc = fmaf(xv[d], ws[h*12+d], acc);
        g_h[(b*H + h)*L + l] = acc;
    }
}

__device__ __forceinline__ void cpow79(float br, float bi, float& pr, float& pi){
    float ar = br, ai = bi;
    float xr = br, xi = bi;
#pragma unroll
    for (int s = 1; s <= 6; s++){
        float nr = xr*xr - xi*xi;
        float ni = 2.0f*xr*xi;
        xr = nr; xi = ni;
        if (s==1 || s==2 || s==3 || s==6){
            float tr = ar*xr - ai*xi;
            float ti = ar*xi + ai*xr;
            ar = tr; ai = ti;
        }
    }
    pr = ar; pi = ai;
}

// fused 3-phase chunked scan + D-skip + GELU; phase-C shuffles batched x4
__global__ __launch_bounds__(256) void scan_fused_kernel(int layer, const float* __restrict__ Dp,
                                                         int do_bn){
    __shared__ float  su[L];
    __shared__ float4 sf[NC][NP+1];
    int bh  = blockIdx.x;
    int h   = bh & (H-1);
    int tid = threadIdx.x;
    int lh  = layer*H + h;
    int c = tid >> 2, q = tid & 3;

    ull rrv[4], riv[4], nriv[4], crv[4], civ[4];
#pragma unroll
    for (int k = 0; k < 4; k++){
        int np = q*4 + k;
        float4 p1 = g_pk1[lh*NP + np];
        float4 p2 = g_pk2[lh*NP + np];
        float2 p3 = g_pk3[lh*NP + np];
        rrv[k]  = pk2(p1.x, p1.y);
        riv[k]  = pk2(p1.z, p1.w);
        nriv[k] = pk2(p2.x, p2.y);
        crv[k]  = pk2(p2.z, p2.w);
        civ[k]  = pk2(p3.x, p3.y);
    }
    float Dh  = Dp[lh];
    float bsc = do_bn ? g_bnscale[h] : 1.0f;
    float bsh = do_bn ? g_bnshift[h] : 0.0f;
    const float4* urow = (const float4*)(g_h + bh*L);
    for (int i = tid; i < L/4; i += 256){
        float4 v = urow[i];
        v.x = fmaf(v.x, bsc, bsh); v.y = fmaf(v.y, bsc, bsh);
        v.z = fmaf(v.z, bsc, bsh); v.w = fmaf(v.w, bsc, bsh);
        *(float4*)&su[i*4] = v;
    }
    __syncthreads();

    int off = c*CT;
    int Tc  = min(CT, L - off);

    ull sr[4], sti[4];
#pragma unroll
    for (int k = 0; k < 4; k++){ sr[k]=0ull; sti[k]=0ull; }

    for (int t = 0; t < Tc; t++){
        float uv = su[off + t];
        ull uu = pk2(uv, uv);
#pragma unroll
        for (int k = 0; k < 4; k++){
            ull tmp = fma2(riv[k], sti[k], uu);
            ull m   = mul2(nriv[k], sr[k]);
            sti[k]  = fma2(rrv[k], sti[k], m);
            sr[k]   = fma2(rrv[k], sr[k], tmp);
        }
    }
#pragma unroll
    for (int k = 0; k < 4; k++){
        float s0,s1,ta,tb; upk2(sr[k],s0,s1); upk2(sti[k],ta,tb);
        sf[c][q*4+k] = make_float4(s0, s1, ta, tb);
    }
    __syncthreads();

    if (tid < NP){
        int np = tid;
        float2 r0 = g_r[lh*N2 + np];
        float2 r1 = g_r[lh*N2 + np + 16];
        float a0r, a0i, a1r, a1i;
        cpow79(r0.x, r0.y, a0r, a0i);
        cpow79(r1.x, r1.y, a1r, a1i);
        float s0r=0.f, s0t=0.f, s1r=0.f, s1t=0.f;
        for (int c2 = 0; c2 < NC; c2++){
            float4 f = sf[c2][np];
            sf[c2][np] = make_float4(s0r, s1r, s0t, s1t);
            float n0r = a0r*s0r + a0i*s0t + f.x;
            float n0t = a0r*s0t - a0i*s0r + f.z;
            float n1r = a1r*s1r + a1i*s1t + f.y;
            float n1t = a1r*s1t - a1i*s1r + f.w;
            s0r=n0r; s0t=n0t; s1r=n1r; s1t=n1t;
        }
    }
    __syncthreads();

#pragma unroll
    for (int k = 0; k < 4; k++){
        float4 v = sf[c][q*4+k];
        sr[k]  = pk2(v.x, v.y);
        sti[k] = pk2(v.z, v.w);
    }
    int t = 0;
    for (int g = 0; g < 19; g++){
        float yp[4], us[4];
#pragma unroll
        for (int i = 0; i < 4; i++){
            int idx = off + t + i;
            float uv = su[idx < L ? idx : (L-1)];
            us[i] = uv;
            ull uu = pk2(uv, uv);
            ull y2 = 0ull;
#pragma unroll
            for (int k = 0; k < 4; k++){
                ull tmp = fma2(riv[k], sti[k], uu);
                ull m   = mul2(nriv[k], sr[k]);
                sti[k]  = fma2(rrv[k], sti[k], m);
                sr[k]   = fma2(rrv[k], sr[k], tmp);
                y2 = fma2(crv[k], sr[k], y2);
                y2 = fma2(civ[k], sti[k], y2);
            }
            float ylo, yhi; upk2(y2, ylo, yhi);
            yp[i] = ylo + yhi;
        }
#pragma unroll
        for (int i = 0; i < 4; i++) yp[i] += __shfl_xor_sync(0xffffffffu, yp[i], 1);
#pragma unroll
        for (int i = 0; i < 4; i++) yp[i] += __shfl_xor_sync(0xffffffffu, yp[i], 2);
#pragma unroll
        for (int i = 0; i < 4; i++){
            int idx = off + t + i;
            if (idx < L) su[idx] = fmaf(us[i], Dh, yp[i]);
        }
        t += 4;
    }
#pragma unroll
    for (int i = 0; i < 3; i++){
        int idx = off + 76 + i;
        float uv = su[idx < L ? idx : (L-1)];
        ull uu = pk2(uv, uv);
        ull y2 = 0ull;
#pragma unroll
        for (int k = 0; k < 4; k++){
            ull tmp = fma2(riv[k], sti[k], uu);
            ull m   = mul2(nriv[k], sr[k]);
            sti[k]  = fma2(rrv[k], sti[k], m);
            sr[k]   = fma2(rrv[k], sr[k], tmp);
            y2 = fma2(crv[k], sr[k], y2);
            y2 = fma2(civ[k], sti[k], y2);
        }
        float ylo, yhi; upk2(y2, ylo, yhi);
        float y = ylo + yhi;
        y += __shfl_xor_sync(0xffffffffu, y, 1);
        y += __shfl_xor_sync(0xffffffffu, y, 2);
        if (idx < L) su[idx] = fmaf(uv, Dh, y);
    }
    __syncthreads();

    float4* orow = (float4*)(g_yg + h*BL + (bh >> 8)*L);
    for (int i = tid; i < L/4; i += 256){
        float4 v = *(const float4*)&su[i*4];
        v.x = gelu1(v.x); v.y = gelu1(v.y); v.z = gelu1(v.z); v.w = gelu1(v.w);
        orow[i] = v;
    }
}

// transpose + bf16-split: g_yg fp32 [k=256][BL] -> g_ybT_{hi,lo} bf16 [BLP][256]
__global__ __launch_bounds__(256) void ytr_kernel(){
    __shared__ float ts[64][65];
    int jt = blockIdx.x;
    int kt = blockIdx.y;
    int tid = threadIdx.x;
    int kr = tid >> 4, jc = tid & 15;
#pragma unroll
    for (int it = 0; it < 4; it++){
        int kk = kr + it*16;
        int k = kt*64 + kk;
        int j = jt*64 + jc*4;
        float4 v = make_float4(0.f,0.f,0.f,0.f);
        if (j < BL) v = *(const float4*)&g_yg[k*BL + j];
        ts[kk][jc*4+0]=v.x; ts[kk][jc*4+1]=v.y; ts[kk][jc*4+2]=v.z; ts[kk][jc*4+3]=v.w;
    }
    __syncthreads();
    int jr = tid >> 2, ks = (tid & 3)*16;
    int j = jt*64 + jr;
    uint32_t ph[8], pl[8];
#pragma unroll
    for (int i = 0; i < 8; i++){
        float v0 = ts[ks + i*2    ][jr];
        float v1 = ts[ks + i*2 + 1][jr];
        __nv_bfloat16 h0 = __float2bfloat16_rn(v0);
        __nv_bfloat16 h1 = __float2bfloat16_rn(v1);
        __nv_bfloat16 l0 = __float2bfloat16_rn(v0 - __bfloat162float(h0));
        __nv_bfloat16 l1 = __float2bfloat16_rn(v1 - __bfloat162float(h1));
        ph[i] = ((uint32_t)__bfloat16_as_ushort(h1) << 16) | __bfloat16_as_ushort(h0);
        pl[i] = ((uint32_t)__bfloat16_as_ushort(l1) << 16) | __bfloat16_as_ushort(l0);
    }
    uint4* dh = (uint4*)(g_ybT_hi + j*H + kt*64 + ks);
    uint4* dl = (uint4*)(g_ybT_lo + j*H + kt*64 + ks);
    dh[0] = make_uint4(ph[0],ph[1],ph[2],ph[3]);
    dh[1] = make_uint4(ph[4],ph[5],ph[6],ph[7]);
    dl[0] = make_uint4(pl[0],pl[1],pl[2],pl[3]);
    dl[1] = make_uint4(pl[4],pl[5],pl[6],pl[7]);
}

// bf16-split mma.sync GEMM, 2-stage cp.async pipeline over 8 K-chunks of 32
// stage layout (32KB): AHI @0, ALO @8K, BHI @16K, BLO @24K; two stages = 64KB
#define SM_STG 32768
#define SM_TOT 65536

__device__ __forceinline__ void stage_tiles(uint32_t sb, int stage, int kc, int tid,
        const __nv_bfloat16* whL, const __nv_bfloat16* wlL, int j0, int g0){
    uint32_t base = sb + stage*SM_STG;
#pragma unroll
    for (int t = 0; t < 2; t++){
        int u = tid + t*256;
        int r = u >> 2, uu = u & 3;
        uint32_t off = (uint32_t)(r*64 + ((uu ^ (r&3))*16));
        int wr = (r < 64) ? (g0*64 + r) : (192 + g0*64 + r);
        int ks = kc*32 + uu*8;
        cpa16(base +         off, whL + (wr*H + ks));
        cpa16(base +  8192 + off, wlL + (wr*H + ks));
        cpa16(base + 16384 + off, g_ybT_hi + ((size_t)(j0 + r)*H + ks));
        cpa16(base + 24576 + off, g_ybT_lo + ((size_t)(j0 + r)*H + ks));
    }
}

__global__ __launch_bounds__(256) void mma_gemm_kernel(const float* __restrict__ bias,
                                                       int layer, int do_bn){
    extern __shared__ char smem[];
    uint32_t sb = smem_u32(smem);
    float* ex = (float*)smem;           // reused post-mainloop (64x132 f32)
    int tid = threadIdx.x;
    int wid = tid >> 5, lane = tid & 31;
    int warp_m = wid >> 2, warp_n = wid & 3;
    int g0 = blockIdx.x;
    int j0 = blockIdx.y * 128;
    const float* bl = bias + layer*2*H;
    const __nv_bfloat16* whL = g_wh + layer*2*H*H;
    const __nv_bfloat16* wlL = g_wl + layer*2*H*H;

    float acc[4][4][4];
#pragma unroll
    for (int mf = 0; mf < 4; mf++)
#pragma unroll
        for (int nf = 0; nf < 4; nf++)
#pragma unroll
            for (int c2 = 0; c2 < 4; c2++) acc[mf][nf][c2] = 0.0f;

    int a_r    = ((lane>>3)&1)*8 + (lane&7);
    int a_kadd = lane>>4;
    int b_r    = lane & 7;
    int b_kadd = (lane>>3)&1;

    stage_tiles(sb, 0, 0, tid, whL, wlL, j0, g0); cpa_commit();
    stage_tiles(sb, 1, 1, tid, whL, wlL, j0, g0); cpa_commit();

#pragma unroll
    for (int kc = 0; kc < 8; kc++){
        if (kc < 7) asm volatile("cp.async.wait_group 1;");
        else        asm volatile("cp.async.wait_group 0;");
        __syncthreads();
        uint32_t base = sb + (kc & 1)*SM_STG;
#pragma unroll
        for (int k16 = 0; k16 < 2; k16++){
            uint32_t bh[4][2], blo[4][2];
#pragma unroll
            for (int nf = 0; nf < 4; nf++){
                int jl = warp_n*32 + nf*8 + b_r;
                uint32_t boff = (uint32_t)(jl*64 + (((k16*2 + b_kadd) ^ (jl&3))*16));
                ldsm_x2(bh[nf],  base + 16384 + boff);
                ldsm_x2(blo[nf], base + 24576 + boff);
            }
#pragma unroll
            for (int mf = 0; mf < 4; mf++){
                int row = warp_m*64 + mf*16 + a_r;
                uint32_t aoff = (uint32_t)(row*64 + (((k16*2 + a_kadd) ^ (row&3))*16));
                uint32_t ah[4], al[4];
                ldsm_x4(ah, base + aoff);
                ldsm_x4(al, base + 8192 + aoff);
#pragma unroll
                for (int nf = 0; nf < 4; nf++){
                    mma16816(acc[mf][nf], ah, bh[nf]);
                    mma16816(acc[mf][nf], ah, blo[nf]);
                    mma16816(acc[mf][nf], al, bh[nf]);
                }
            }
        }
        __syncthreads();
        if (kc + 2 < 8){
            stage_tiles(sb, kc & 1, kc + 2, tid, whL, wlL, j0, g0);
            cpa_commit();
        }
    }

    int gr = lane >> 2, gc2 = (lane & 3)*2;
    if (warp_m == 1){
#pragma unroll
        for (int mf = 0; mf < 4; mf++)
#pragma unroll
        for (int nf = 0; nf < 4; nf++)
#pragma unroll
        for (int c2 = 0; c2 < 4; c2++){
            int rl = mf*16 + gr + (c2>>1)*8;
            int col = warp_n*32 + nf*8 + gc2 + (c2&1);
            ex[rl*132 + col] = acc[mf][nf][c2];
        }
    }
    __syncthreads();
    if (warp_m == 0){
#pragma unroll
        for (int mf = 0; mf < 4; mf++)
#pragma unroll
        for (int nf = 0; nf < 4; nf++)
#pragma unroll
        for (int c2 = 0; c2 < 4; c2++){
            int rl = mf*16 + gr + (c2>>1)*8;
            int col = warp_n*32 + nf*8 + gc2 + (c2&1);
            int ga = g0*64 + rl;
            float a = acc[mf][nf][c2] + bl[ga];
            float b = ex[rl*132 + col] + bl[256 + ga];
            float glu = a * (1.0f/(1.0f + expf(-b)));
            int j = j0 + col;
            if (j < BL){
                int bb = j / L, l = j - bb*L;
                int idx = (bb*H + ga)*L + l;
                float sc = do_bn ? g_bnscale[ga] : 1.0f;
                float sh = do_bn ? g_bnshift[ga] : 0.0f;
                g_h[idx] = fmaf(g_h[idx], sc, sh) + glu;
            }
        }
    }
}

__global__ void bn_stats_kernel(){
    __shared__ double ssum[256], ssq[256];
    int h = blockIdx.x;
    int half = blockIdx.y;
    int tid = threadIdx.x;
    double s = 0.0, q = 0.0;
    for (int i = tid; i < 4*L; i += 256){
        int b = half*4 + i / L, l = i % L;
        float v = g_h[(b*H + h)*L + l];
        s += v; q += (double)v*(double)v;
    }
    ssum[tid] = s; ssq[tid] = q;
    __syncthreads();
    for (int st = 128; st > 0; st >>= 1){
        if (tid < st){ ssum[tid] += ssum[tid+st]; ssq[tid] += ssq[tid+st]; }
        __syncthreads();
    }
    if (tid == 0){
        atomicAdd(&g_bnsum[h], ssum[0]);
        atomicAdd(&g_bnsq[h],  ssq[0]);
    }
}

__global__ void bn_finalize_kernel(const float* __restrict__ gamma, const float* __restrict__ beta,
                                   int bnidx){
    int h = threadIdx.x;
    double mean = g_bnsum[h] / (double)(NB*L);
    double var  = g_bnsq[h] / (double)(NB*L) - mean*mean;
    float scale = gamma[bnidx*H + h] * (float)(1.0 / sqrt(var + 1e-5));
    g_bnscale[h] = scale;
    g_bnshift[h] = beta[bnidx*H + h] - (float)mean * scale;
    g_bnsum[h] = 0.0;
    g_bnsq[h]  = 0.0;
}

__global__ void transpose_kernel(float* __restrict__ out){
    __shared__ float tile[32][33];
    int b = blockIdx.z;
    int l0 = blockIdx.x*32, h0 = blockIdx.y*32;
    int tx = threadIdx.x, ty = threadIdx.y;
    for (int i = ty; i < 32; i += 8){
        int l = l0 + tx;
        tile[i][tx] = (l < L) ? g_h[(b*H + h0 + i)*L + l] : 0.0f;
    }
    __syncthreads();
    for (int i = ty; i < 32; i += 8){
        int l = l0 + i;
        if (l < L) out[(b*L + l)*H + h0 + tx] = tile[tx][i];
    }
}

extern "C" void kernel_launch(void* const* d_in, const int* in_sizes, int n_in,
                              void* d_out, int out_size){
    const float* x      = (const float*)d_in[0];
    const float* pre_w  = (const float*)d_in[1];
    const float* pre_b  = (const float*)d_in[2];
    const float* log_dt = (const float*)d_in[3];
    const float* C_re   = (const float*)d_in[4];
    const float* C_im   = (const float*)d_in[5];
    const float* logA   = (const float*)d_in[6];
    const float* Aim    = (const float*)d_in[7];
    const float* Dp     = (const float*)d_in[8];
    const float* out_w  = (const float*)d_in[9];
    const float* out_b  = (const float*)d_in[10];
    const float* bn_g   = (const float*)d_in[11];
    const float* bn_b   = (const float*)d_in[12];
    float* out = (float*)d_out;

    cudaFuncSetAttribute(mma_gemm_kernel, cudaFuncAttributeMaxDynamicSharedMemorySize, SM_TOT);

    params_kernel<<<96, 256>>>(log_dt, C_re, C_im, logA, Aim);
    wconv_kernel<<<(NL*2*H*H + 255)/256, 256>>>(out_w);
    preproj_kernel<<<dim3(40, 8), 128>>>(x, pre_w, pre_b);
    for (int layer = 0; layer < NL; layer++){
        int do_bn = (layer > 0) && (((layer - 1) & 1) == 0);
        scan_fused_kernel<<<NB*H, 256>>>(layer, Dp, do_bn);
        ytr_kernel<<<dim3(BLP/64, 4), 256>>>();
        mma_gemm_kernel<<<dim3(4, BLP/128), 256, SM_TOT>>>(out_b, layer, do_bn);
        if ((layer & 1) == 0){
            bn_stats_kernel<<<dim3(H, 2), 256>>>();
            bn_finalize_kernel<<<1, H>>>(bn_g, bn_b, layer/2);
        }
    }
    transpose_kernel<<<dim3((L + 31)/32, H/32, NB), dim3(32, 8)>>>(out);
}

// round 13
// speedup vs baseline: 1.0911x; 1.0863x over previous
#include <cuda_runtime.h>
#include <math.h>
#include <stdint.h>

#define NB   8
#define L    5000
#define DIN  12
#define H    256
#define N2   32
#define NL   6
#define NC   64
#define CT   79
#define BL   (NB*L)
#define NP   16

typedef unsigned long long ull;

__device__ __forceinline__ ull fma2(ull a, ull b, ull c){ ull d; asm("fma.rn.f32x2 %0,%1,%2,%3;":"=l"(d):"l"(a),"l"(b),"l"(c)); return d; }
__device__ __forceinline__ ull mul2(ull a, ull b){ ull d; asm("mul.rn.f32x2 %0,%1,%2;":"=l"(d):"l"(a),"l"(b)); return d; }
__device__ __forceinline__ ull pk2(float lo, float hi){ ull r; asm("mov.b64 %0,{%1,%2};":"=l"(r):"f"(lo),"f"(hi)); return r; }
__device__ __forceinline__ void upk2(ull v, float& lo, float& hi){ asm("mov.b64 {%0,%1},%2;":"=f"(lo),"=f"(hi):"l"(v)); }
__device__ __forceinline__ void cpa16(uint32_t dst, const float* src){
    asm volatile("cp.async.cg.shared.global [%0], [%1], 16;"::"r"(dst),"l"(src));
}
__device__ __forceinline__ void cpa_commit(){ asm volatile("cp.async.commit_group;"); }
__device__ __forceinline__ void cpa_wait0(){ asm volatile("cp.async.wait_group 0;"); }
__device__ __forceinline__ float gelu1(float y){ return 0.5f*y*(1.0f + erff(y*0.70710678118654752f)); }

// ---- scratch ----
__device__ float  g_h[NB*H*L];
__device__ float  g_yg[H*BL + 128];
__device__ float4 g_pk1[NL*H*NP];   // rr0,rr1,ri0,ri1
__device__ float4 g_pk2[NL*H*NP];   // -ri0,-ri1,cr0,cr1
__device__ float2 g_pk3[NL*H*NP];   // ci0,ci1
__device__ float2 g_r  [NL*H*N2];
__device__ float  g_bnscale[H];
__device__ float  g_bnshift[H];
__device__ double g_bnsum[H];
__device__ double g_bnsq[H];

__global__ void params_kernel(const float* __restrict__ log_dt, const float* __restrict__ C_re,
                              const float* __restrict__ C_im, const float* __restrict__ logA,
                              const float* __restrict__ Aim){
    int idx = blockIdx.x*blockDim.x + threadIdx.x;
    if (idx >= NL*H*NP) return;
    int np = idx & (NP-1);
    int lh = idx >> 4;
    float dt = expf(log_dt[lh]);
    float rr[2], ri[2], cr[2], ci[2];
#pragma unroll
    for (int k = 0; k < 2; k++){
        int pi = lh*N2 + np + k*16;
        float Ar = -expf(logA[pi]);
        float Ai = Aim[pi];
        float er = expf(dt*Ar);
        float rre = er*cosf(dt*Ai), rim = er*sinf(dt*Ai);
        float e1r = rre - 1.0f, e1i = rim;
        float cre = C_re[pi], cim = C_im[pi];
        float tr = cre*e1r - cim*e1i;
        float ti = cre*e1i + cim*e1r;
        float inv = 1.0f/(Ar*Ar + Ai*Ai);
        float Cdr = (tr*Ar + ti*Ai)*inv;
        float Cdi = (ti*Ar - tr*Ai)*inv;
        rr[k]=rre; ri[k]=rim; cr[k]=2.0f*Cdr; ci[k]=2.0f*Cdi;
        g_r[pi] = make_float2(rre, rim);
    }
    g_pk1[idx] = make_float4(rr[0], rr[1], ri[0], ri[1]);
    g_pk2[idx] = make_float4(-ri[0], -ri[1], cr[0], cr[1]);
    g_pk3[idx] = make_float2(ci[0], ci[1]);
}

__global__ void preproj_kernel(const float* __restrict__ x, const float* __restrict__ w,
                               const float* __restrict__ bias){
    __shared__ float xs[128*13];
    __shared__ float ws[H*12];
    __shared__ float bs[H];
    int b = blockIdx.y;
    int l0 = blockIdx.x*128;
    int tid = threadIdx.x;
    for (int i = tid; i < H*12; i += 128) ws[i] = w[i];
    for (int i = tid; i < H;    i += 128) bs[i] = bias[i];
    for (int i = tid; i < 128*12; i += 128){
        int ll = i/12, d = i - ll*12;
        int l = l0 + ll;
        xs[ll*13+d] = (l < L) ? x[(b*L + l)*12 + d] : 0.0f;
    }
    __syncthreads();
    int l = l0 + tid;
    if (l >= L) return;
    float xv[12];
#pragma unroll
    for (int d = 0; d < 12; d++) xv[d] = xs[tid*13+d];
    for (int h = 0; h < H; h++){
        float acc = bs[h];
#pragma unroll
        for (int d = 0; d < 12; d++) acc = fmaf(xv[d], ws[h*12+d], acc);
        g_h[(b*H + h)*L + l] = acc;
    }
}

__device__ __forceinline__ void cpow79(float br, float bi, float& pr, float& pi){
    float ar = br, ai = bi;
    float xr = br, xi = bi;
#pragma unroll
    for (int s = 1; s <= 6; s++){
        float nr = xr*xr - xi*xi;
        float ni = 2.0f*xr*xi;
        xr = nr; xi = ni;
        if (s==1 || s==2 || s==3 || s==6){
            float tr = ar*xr - ai*xi;
            float ti = ar*xi + ai*xr;
            ar = tr; ai = ti;
        }
    }
    pr = ar; pi = ai;
}

// fused 3-phase chunked scan + D-skip + GELU
// warps 0-6: clamp-free fixed-count paths; warp 7: ragged path
__global__ __launch_bounds__(256) void scan_fused_kernel(int layer, const float* __restrict__ Dp,
                                                         int do_bn){
    __shared__ float  su[L];
    __shared__ float4 sf[NC][NP+1];
    int bh  = blockIdx.x;
    int h   = bh & (H-1);
    int tid = threadIdx.x;
    int lh  = layer*H + h;
    int c = tid >> 2, q = tid & 3;

    ull rrv[4], riv[4], nriv[4], crv[4], civ[4];
#pragma unroll
    for (int k = 0; k < 4; k++){
        int np = q*4 + k;
        float4 p1 = g_pk1[lh*NP + np];
        float4 p2 = g_pk2[lh*NP + np];
        float2 p3 = g_pk3[lh*NP + np];
        rrv[k]  = pk2(p1.x, p1.y);
        riv[k]  = pk2(p1.z, p1.w);
        nriv[k] = pk2(p2.x, p2.y);
        crv[k]  = pk2(p2.z, p2.w);
        civ[k]  = pk2(p3.x, p3.y);
    }
    float Dh  = Dp[lh];
    float bsc = do_bn ? g_bnscale[h] : 1.0f;
    float bsh = do_bn ? g_bnshift[h] : 0.0f;
    const float4* urow = (const float4*)(g_h + bh*L);
    for (int i = tid; i < L/4; i += 256){
        float4 v = urow[i];
        v.x = fmaf(v.x, bsc, bsh); v.y = fmaf(v.y, bsc, bsh);
        v.z = fmaf(v.z, bsc, bsh); v.w = fmaf(v.w, bsc, bsh);
        *(float4*)&su[i*4] = v;
    }
    __syncthreads();

    int off = c*CT;
    int Tc  = min(CT, L - off);

    ull sr[4], sti[4];
#pragma unroll
    for (int k = 0; k < 4; k++){ sr[k]=0ull; sti[k]=0ull; }

    // phase A: chunk-local final states
    if (tid < 224){
#pragma unroll 4
        for (int t = 0; t < CT; t++){
            float uv = su[off + t];
            ull uu = pk2(uv, uv);
#pragma unroll
            for (int k = 0; k < 4; k++){
                ull tmp = fma2(riv[k], sti[k], uu);
                ull m   = mul2(nriv[k], sr[k]);
                sti[k]  = fma2(rrv[k], sti[k], m);
                sr[k]   = fma2(rrv[k], sr[k], tmp);
            }
        }
    } else {
        for (int t = 0; t < Tc; t++){
            float uv = su[off + t];
            ull uu = pk2(uv, uv);
#pragma unroll
            for (int k = 0; k < 4; k++){
                ull tmp = fma2(riv[k], sti[k], uu);
                ull m   = mul2(nriv[k], sr[k]);
                sti[k]  = fma2(rrv[k], sti[k], m);
                sr[k]   = fma2(rrv[k], sr[k], tmp);
            }
        }
    }
#pragma unroll
    for (int k = 0; k < 4; k++){
        float s0,s1,ta,tb; upk2(sr[k],s0,s1); upk2(sti[k],ta,tb);
        sf[c][q*4+k] = make_float4(s0, s1, ta, tb);
    }
    __syncthreads();

    // phase B: serial boundary propagation
    if (tid < NP){
        int np = tid;
        float2 r0 = g_r[lh*N2 + np];
        float2 r1 = g_r[lh*N2 + np + 16];
        float a0r, a0i, a1r, a1i;
        cpow79(r0.x, r0.y, a0r, a0i);
        cpow79(r1.x, r1.y, a1r, a1i);
        float s0r=0.f, s0t=0.f, s1r=0.f, s1t=0.f;
        for (int c2 = 0; c2 < NC; c2++){
            float4 f = sf[c2][np];
            sf[c2][np] = make_float4(s0r, s1r, s0t, s1t);
            float n0r = a0r*s0r + a0i*s0t + f.x;
            float n0t = a0r*s0t - a0i*s0r + f.z;
            float n1r = a1r*s1r + a1i*s1t + f.y;
            float n1t = a1r*s1t - a1i*s1r + f.w;
            s0r=n0r; s0t=n0t; s1r=n1r; s1t=n1t;
        }
    }
    __syncthreads();

    // phase C: replay with output, shuffle batched x4
#pragma unroll
    for (int k = 0; k < 4; k++){
        float4 v = sf[c][q*4+k];
        sr[k]  = pk2(v.x, v.y);
        sti[k] = pk2(v.z, v.w);
    }
    if (tid < 224){
        // clean path: no clamps, no guards
        int t = 0;
        for (int g = 0; g < 19; g++){
            float yp[4], us[4];
            us[0] = su[off+t]; us[1] = su[off+t+1]; us[2] = su[off+t+2]; us[3] = su[off+t+3];
#pragma unroll
            for (int i = 0; i < 4; i++){
                ull uu = pk2(us[i], us[i]);
                ull y2 = 0ull;
#pragma unroll
                for (int k = 0; k < 4; k++){
                    ull tmp = fma2(riv[k], sti[k], uu);
                    ull m   = mul2(nriv[k], sr[k]);
                    sti[k]  = fma2(rrv[k], sti[k], m);
                    sr[k]   = fma2(rrv[k], sr[k], tmp);
                    y2 = fma2(crv[k], sr[k], y2);
                    y2 = fma2(civ[k], sti[k], y2);
                }
                float ylo, yhi; upk2(y2, ylo, yhi);
                yp[i] = ylo + yhi;
            }
#pragma unroll
            for (int i = 0; i < 4; i++) yp[i] += __shfl_xor_sync(0xffffffffu, yp[i], 1);
#pragma unroll
            for (int i = 0; i < 4; i++) yp[i] += __shfl_xor_sync(0xffffffffu, yp[i], 2);
#pragma unroll
            for (int i = 0; i < 4; i++) su[off+t+i] = fmaf(us[i], Dh, yp[i]);
            t += 4;
        }
#pragma unroll
        for (int i = 0; i < 3; i++){
            float uv = su[off + 76 + i];
            ull uu = pk2(uv, uv);
            ull y2 = 0ull;
#pragma unroll
            for (int k = 0; k < 4; k++){
                ull tmp = fma2(riv[k], sti[k], uu);
                ull m   = mul2(nriv[k], sr[k]);
                sti[k]  = fma2(rrv[k], sti[k], m);
                sr[k]   = fma2(rrv[k], sr[k], tmp);
                y2 = fma2(crv[k], sr[k], y2);
                y2 = fma2(civ[k], sti[k], y2);
            }
            float ylo, yhi; upk2(y2, ylo, yhi);
            float y = ylo + yhi;
            y += __shfl_xor_sync(0xffffffffu, y, 1);
            y += __shfl_xor_sync(0xffffffffu, y, 2);
            su[off + 76 + i] = fmaf(uv, Dh, y);
        }
    } else {
        // ragged path (warp 7): clamped
        int t = 0;
        for (int g = 0; g < 19; g++){
            float yp[4], us[4];
#pragma unroll
            for (int i = 0; i < 4; i++){
                int idx = off + t + i;
                float uv = su[idx < L ? idx : (L-1)];
                us[i] = uv;
                ull uu = pk2(uv, uv);
                ull y2 = 0ull;
#pragma unroll
                for (int k = 0; k < 4; k++){
                    ull tmp = fma2(riv[k], sti[k], uu);
                    ull m   = mul2(nriv[k], sr[k]);
                    sti[k]  = fma2(rrv[k], sti[k], m);
                    sr[k]   = fma2(rrv[k], sr[k], tmp);
                    y2 = fma2(crv[k], sr[k], y2);
                    y2 = fma2(civ[k], sti[k], y2);
                }
                float ylo, yhi; upk2(y2, ylo, yhi);
                yp[i] = ylo + yhi;
            }
#pragma unroll
            for (int i = 0; i < 4; i++) yp[i] += __shfl_xor_sync(0xffffffffu, yp[i], 1);
#pragma unroll
            for (int i = 0; i < 4; i++) yp[i] += __shfl_xor_sync(0xffffffffu, yp[i], 2);
#pragma unroll
            for (int i = 0; i < 4; i++){
                int idx = off + t + i;
                if (idx < L) su[idx] = fmaf(us[i], Dh, yp[i]);
            }
            t += 4;
        }
#pragma unroll
        for (int i = 0; i < 3; i++){
            int idx = off + 76 + i;
            float uv = su[idx < L ? idx : (L-1)];
            ull uu = pk2(uv, uv);
            ull y2 = 0ull;
#pragma unroll
            for (int k = 0; k < 4; k++){
                ull tmp = fma2(riv[k], sti[k], uu);
                ull m   = mul2(nriv[k], sr[k]);
                sti[k]  = fma2(rrv[k], sti[k], m);
                sr[k]   = fma2(rrv[k], sr[k], tmp);
                y2 = fma2(crv[k], sr[k], y2);
                y2 = fma2(civ[k], sti[k], y2);
            }
            float ylo, yhi; upk2(y2, ylo, yhi);
            float y = ylo + yhi;
            y += __shfl_xor_sync(0xffffffffu, y, 1);
            y += __shfl_xor_sync(0xffffffffu, y, 2);
            if (idx < L) su[idx] = fmaf(uv, Dh, y);
        }
    }
    __syncthreads();

    float4* orow = (float4*)(g_yg + h*BL + (bh >> 8)*L);
    for (int i = tid; i < L/4; i += 256){
        float4 v = *(const float4*)&su[i*4];
        v.x = gelu1(v.x); v.y = gelu1(v.y); v.z = gelu1(v.z); v.w = gelu1(v.w);
        orow[i] = v;
    }
}

// 1x1 conv GEMM + GLU + BN-of-residual-base + residual add + fused BN stats
__global__ __launch_bounds__(256, 2) void glu_gemm_kernel(const float* __restrict__ Wg,
                                                          const float* __restrict__ bias,
                                                          int layer, int do_bn, int do_stats){
    __shared__ float Ys[2][16][128];
    __shared__ ull   Wap[2][16][66];
    __shared__ ull   Wbp[2][16][66];
    const float* Wl = Wg + layer*2*H*H;
    const float* bl = bias + layer*2*H;
    int j0 = blockIdx.x*128;
    int g0 = blockIdx.y*64;
    int tid = threadIdx.x;
    int tx = tid & 15, ty = tid >> 4;
    int wg = tid >> 2, wsub = tid & 3;
    int yr = tid >> 5, yseg = tid & 31;
    const float* ysrcA = g_yg + yr*BL + j0 + yseg*4;
    uint32_t ysA = (uint32_t)__cvta_generic_to_shared(&Ys[0][0][0]) + yr*512 + yseg*16;

    ull accA[4][4], accB[4][4];
#pragma unroll
    for (int i = 0; i < 4; i++)
#pragma unroll
        for (int cc = 0; cc < 4; cc++){ accA[i][cc]=0ull; accB[i][cc]=0ull; }

    float4 wa = *(const float4*)&Wl[(g0 + wg)*H + wsub*4];
    float4 wb = *(const float4*)&Wl[(H + g0 + wg)*H + wsub*4];
    cpa16(ysA,         ysrcA);
    cpa16(ysA + 8*512, ysrcA + 8*BL);
    cpa_commit();
    Wap[0][wsub*4+0][wg]=pk2(wa.x,wa.x); Wap[0][wsub*4+1][wg]=pk2(wa.y,wa.y);
    Wap[0][wsub*4+2][wg]=pk2(wa.z,wa.z); Wap[0][wsub*4+3][wg]=pk2(wa.w,wa.w);
    Wbp[0][wsub*4+0][wg]=pk2(wb.x,wb.x); Wbp[0][wsub*4+1][wg]=pk2(wb.y,wb.y);
    Wbp[0][wsub*4+2][wg]=pk2(wb.z,wb.z); Wbp[0][wsub*4+3][wg]=pk2(wb.w,wb.w);
    cpa_wait0();
    __syncthreads();

    for (int ko = 0; ko < H; ko += 16){
        int cur = (ko >> 4) & 1;
        bool more = (ko + 16 < H);
        if (more){
            wa = *(const float4*)&Wl[(g0 + wg)*H + (ko+16) + wsub*4];
            wb = *(const float4*)&Wl[(H + g0 + wg)*H + (ko+16) + wsub*4];
            uint32_t dst = ysA + (cur^1)*8192;
            const float* src = ysrcA + (ko+16)*BL;
            cpa16(dst,         src);
            cpa16(dst + 8*512, src + 8*BL);
            cpa_commit();
        }
        const float* Yc = &Ys[cur][0][0];
        const ull* Wac = &Wap[cur][0][0];
        const ull* Wbc = &Wbp[cur][0][0];
#pragma unroll
        for (int kk = 0; kk < 16; kk++){
            ull yv[4];
#pragma unroll
            for (int cc = 0; cc < 4; cc++) yv[cc] = *(const ull*)(Yc + kk*128 + cc*32 + tx*2);
            ulonglong2 wa01 = *(const ulonglong2*)(Wac + kk*66 + ty*4);
            ulonglong2 wa23 = *(const ulonglong2*)(Wac + kk*66 + ty*4 + 2);
            ulonglong2 wb01 = *(const ulonglong2*)(Wbc + kk*66 + ty*4);
            ulonglong2 wb23 = *(const ulonglong2*)(Wbc + kk*66 + ty*4 + 2);
            ull wa_[4] = {wa01.x, wa01.y, wa23.x, wa23.y};
            ull wb_[4] = {wb01.x, wb01.y, wb23.x, wb23.y};
#pragma unroll
            for (int i = 0; i < 4; i++)
#pragma unroll
                for (int cc = 0; cc < 4; cc++){
                    accA[i][cc] = fma2(wa_[i], yv[cc], accA[i][cc]);
                    accB[i][cc] = fma2(wb_[i], yv[cc], accB[i][cc]);
                }
        }
        if (more){
            int nxt = cur^1;
            Wap[nxt][wsub*4+0][wg]=pk2(wa.x,wa.x); Wap[nxt][wsub*4+1][wg]=pk2(wa.y,wa.y);
            Wap[nxt][wsub*4+2][wg]=pk2(wa.z,wa.z); Wap[nxt][wsub*4+3][wg]=pk2(wa.w,wa.w);
            Wbp[nxt][wsub*4+0][wg]=pk2(wb.x,wb.x); Wbp[nxt][wsub*4+1][wg]=pk2(wb.y,wb.y);
            Wbp[nxt][wsub*4+2][wg]=pk2(wb.z,wb.z); Wbp[nxt][wsub*4+3][wg]=pk2(wb.w,wb.w);
            cpa_wait0();
            __syncthreads();
        }
    }

#pragma unroll
    for (int i = 0; i < 4; i++){
        int ga = g0 + ty*4 + i;
        float ba = bl[ga], bb = bl[H + ga];
        float sc = do_bn ? g_bnscale[ga] : 1.0f;
        float sh = do_bn ? g_bnshift[ga] : 0.0f;
        double dsum = 0.0, dsq = 0.0;
#pragma unroll
        for (int cc = 0; cc < 4; cc++){
            int j = j0 + cc*32 + tx*2;
            float a0,a1,b0,b1;
            upk2(accA[i][cc], a0, a1);
            upk2(accB[i][cc], b0, b1);
            a0 += ba; a1 += ba; b0 += bb; b1 += bb;
            float gl0 = a0 * (1.0f/(1.0f+expf(-b0)));
            float gl1 = a1 * (1.0f/(1.0f+expf(-b1)));
            if (j < BL){
                int b = j / L, l = j - b*L;
                int idx = (b*H + ga)*L + l;
                float hn = fmaf(g_h[idx], sc, sh) + gl0;
                g_h[idx] = hn;
                dsum += hn; dsq += (double)hn*(double)hn;
            }
            if (j + 1 < BL){
                int b = (j+1) / L, l = (j+1) - b*L;
                int idx = (b*H + ga)*L + l;
                float hn = fmaf(g_h[idx], sc, sh) + gl1;
                g_h[idx] = hn;
                dsum += hn; dsq += (double)hn*(double)hn;
            }
        }
        if (do_stats){
#pragma unroll
            for (int o = 1; o < 16; o <<= 1){
                dsum += __shfl_xor_sync(0xffffffffu, dsum, o);
                dsq  += __shfl_xor_sync(0xffffffffu, dsq,  o);
            }
            if ((tid & 15) == 0){
                atomicAdd(&g_bnsum[ga], dsum);
                atomicAdd(&g_bnsq[ga],  dsq);
            }
        }
    }
}

__global__ void bn_finalize_kernel(const float* __restrict__ gamma, const float* __restrict__ beta,
                                   int bnidx){
    int h = threadIdx.x;
    double mean = g_bnsum[h] / (double)(NB*L);
    double var  = g_bnsq[h] / (double)(NB*L) - mean*mean;
    float scale = gamma[bnidx*H + h] * (float)(1.0 / sqrt(var + 1e-5));
    g_bnscale[h] = scale;
    g_bnshift[h] = beta[bnidx*H + h] - (float)mean * scale;
    g_bnsum[h] = 0.0;   // re-zero for next use (graph-replay safe)
    g_bnsq[h]  = 0.0;
}

__global__ void transpose_kernel(float* __restrict__ out){
    __shared__ float tile[32][33];
    int b = blockIdx.z;
    int l0 = blockIdx.x*32, h0 = blockIdx.y*32;
    int tx = threadIdx.x, ty = threadIdx.y;
    for (int i = ty; i < 32; i += 8){
        int l = l0 + tx;
        tile[i][tx] = (l < L) ? g_h[(b*H + h0 + i)*L + l] : 0.0f;
    }
    __syncthreads();
    for (int i = ty; i < 32; i += 8){
        int l = l0 + i;
        if (l < L) out[(b*L + l)*H + h0 + tx] = tile[tx][i];
    }
}

extern "C" void kernel_launch(void* const* d_in, const int* in_sizes, int n_in,
                              void* d_out, int out_size){
    const float* x      = (const float*)d_in[0];
    const float* pre_w  = (const float*)d_in[1];
    const float* pre_b  = (const float*)d_in[2];
    const float* log_dt = (const float*)d_in[3];
    const float* C_re   = (const float*)d_in[4];
    const float* C_im   = (const float*)d_in[5];
    const float* logA   = (const float*)d_in[6];
    const float* Aim    = (const float*)d_in[7];
    const float* Dp     = (const float*)d_in[8];
    const float* out_w  = (const float*)d_in[9];
    const float* out_b  = (const float*)d_in[10];
    const float* bn_g   = (const float*)d_in[11];
    const float* bn_b   = (const float*)d_in[12];
    float* out = (float*)d_out;

    params_kernel<<<96, 256>>>(log_dt, C_re, C_im, logA, Aim);
    preproj_kernel<<<dim3(40, 8), 128>>>(x, pre_w, pre_b);
    for (int layer = 0; layer < NL; layer++){
        int do_bn    = (layer > 0) && (((layer - 1) & 1) == 0);   // layers 1,3,5 consume BN of 0,2,4
        int do_stats = ((layer & 1) == 0);                        // layers 0,2,4 produce stats
        scan_fused_kernel<<<NB*H, 256>>>(layer, Dp, do_bn);
        glu_gemm_kernel<<<dim3((BL + 127)/128, 4), 256>>>(out_w, out_b, layer, do_bn, do_stats);
        if (do_stats) bn_finalize_kernel<<<1, H>>>(bn_g, bn_b, layer/2);
    }
    transpose_kernel<<<dim3((L + 31)/32, H/32, NB), dim3(32, 8)>>>(out);
}